// round 7
// baseline (speedup 1.0000x reference)
#include <cuda_runtime.h>
#include <cuda_bf16.h>
#include <cstdint>

#define N_NODES 100000
#define N_EDGES 1600000
#define C       128
#define C4      32
#define BM      128
#define KC      32
#define SA_STR  36
#define SB2_STR 132        // float2 stride for paired-B smem

// ---------------- scratch ----------------
__device__ float4 g_mean[(size_t)N_NODES * C4];   // fp32 mean (MMA A operand)
__device__ float4 g_h1 [(size_t)N_NODES * C4];    // fp32 h1 (MMA A operand)
__device__ float4 g_h2 [(size_t)N_NODES * C4];
__device__ uint2  g_xb [(size_t)N_NODES * C4];    // bf16 x   (gather operand)
__device__ uint2  g_h1b[(size_t)N_NODES * C4];    // bf16 h1  (gather operand)
__device__ int    g_deg [N_NODES];
__device__ int    g_cur [N_NODES];
__device__ int    g_off [N_NODES + 1];
__device__ int    g_srcs[N_EDGES];

// ---------------- helpers ----------------
__device__ __forceinline__ float to_tf32(float x) {
    uint32_t u;
    asm("cvt.rna.tf32.f32 %0, %1;" : "=r"(u) : "f"(x));
    return __uint_as_float(u);
}
__device__ __forceinline__ void mma8(float* c,
                                     uint32_t a0, uint32_t a1, uint32_t a2, uint32_t a3,
                                     uint32_t b0, uint32_t b1) {
    asm volatile("mma.sync.aligned.m16n8k8.row.col.f32.tf32.tf32.f32 "
                 "{%0,%1,%2,%3}, {%4,%5,%6,%7}, {%8,%9}, {%0,%1,%2,%3};"
                 : "+f"(c[0]), "+f"(c[1]), "+f"(c[2]), "+f"(c[3])
                 : "r"(a0), "r"(a1), "r"(a2), "r"(a3), "r"(b0), "r"(b1));
}
__device__ __forceinline__ float2 bf2f(unsigned u) {
    __nv_bfloat162 b = *reinterpret_cast<__nv_bfloat162*>(&u);
    return __bfloat1622float2(b);
}
__device__ __forceinline__ unsigned f2bf(float a, float b) {
    __nv_bfloat162 v = __float22bfloat162_rn(make_float2(a, b));
    return *reinterpret_cast<unsigned*>(&v);
}
__device__ __forceinline__ void addbf(float4& a, uint2 v) {
    float2 lo = bf2f(v.x), hi = bf2f(v.y);
    a.x += lo.x; a.y += lo.y; a.z += hi.x; a.w += hi.y;
}

// ================= x -> bf16 =================
__global__ void k_cvt_x(const float4* __restrict__ x) {
    int i = blockIdx.x * blockDim.x + threadIdx.x;
    if (i >= N_NODES * C4) return;
    float4 v = __ldg(x + i);
    g_xb[i] = make_uint2(f2bf(v.x, v.y), f2bf(v.z, v.w));
}

// ================= CSR build =================
__global__ void k_csr_init() {
    int i = blockIdx.x * blockDim.x + threadIdx.x;
    int stride = gridDim.x * blockDim.x;
    for (int j = i; j < N_NODES; j += stride) { g_deg[j] = 0; g_cur[j] = 0; }
}

__global__ void k_hist(const int* __restrict__ ei) {
    int e = blockIdx.x * blockDim.x + threadIdx.x;
    if (e >= N_EDGES) return;
    atomicAdd(g_deg + ei[N_EDGES + e], 1);
}

__global__ void __launch_bounds__(1024)
k_scan() {
    __shared__ int s_wsum[32];
    __shared__ int s_carry;
    int tid = threadIdx.x, lane = tid & 31, wid = tid >> 5;
    if (tid == 0) { s_carry = 0; g_off[0] = 0; }
    __syncthreads();

    for (int base = 0; base < N_NODES; base += 4096) {
        int i0 = base + tid * 4;
        int d0 = (i0 + 0 < N_NODES) ? g_deg[i0 + 0] : 0;
        int d1 = (i0 + 1 < N_NODES) ? g_deg[i0 + 1] : 0;
        int d2 = (i0 + 2 < N_NODES) ? g_deg[i0 + 2] : 0;
        int d3 = (i0 + 3 < N_NODES) ? g_deg[i0 + 3] : 0;
        int tot = d0 + d1 + d2 + d3;

        int s = tot;
        #pragma unroll
        for (int o = 1; o < 32; o <<= 1) {
            int t = __shfl_up_sync(0xffffffffu, s, o);
            if (lane >= o) s += t;
        }
        if (lane == 31) s_wsum[wid] = s;
        __syncthreads();
        if (wid == 0) {
            int w = s_wsum[lane];
            #pragma unroll
            for (int o = 1; o < 32; o <<= 1) {
                int t = __shfl_up_sync(0xffffffffu, w, o);
                if (lane >= o) w += t;
            }
            s_wsum[lane] = w;
        }
        __syncthreads();

        int excl = s_carry + (wid ? s_wsum[wid - 1] : 0) + s - tot;
        if (i0 + 0 < N_NODES) g_off[i0 + 1] = excl + d0;
        if (i0 + 1 < N_NODES) g_off[i0 + 2] = excl + d0 + d1;
        if (i0 + 2 < N_NODES) g_off[i0 + 3] = excl + d0 + d1 + d2;
        if (i0 + 3 < N_NODES) g_off[i0 + 4] = excl + tot;

        __syncthreads();
        if (tid == 0) s_carry += s_wsum[31];
        __syncthreads();
    }
}

__global__ void k_fill(const int* __restrict__ ei) {
    int e = blockIdx.x * blockDim.x + threadIdx.x;
    if (e >= N_EDGES) return;
    int srcv = ei[e];
    int d    = ei[N_EDGES + e];
    int pos  = atomicAdd(g_cur + d, 1);
    g_srcs[g_off[d] + pos] = srcv;
}

// ================= aggregation (bf16 gather, shfl-free) =================
__global__ void __launch_bounds__(256)
k_agg(int use_x) {
    const uint2* __restrict__ hb = use_x ? (const uint2*)g_xb : (const uint2*)g_h1b;
    int node = (blockIdx.x * blockDim.x + threadIdx.x) >> 5;
    if (node >= N_NODES) return;
    int lane = threadIdx.x & 31;

    int beg = __ldg(g_off + node);
    int end = __ldg(g_off + node + 1);

    float4 a0 = make_float4(0.f, 0.f, 0.f, 0.f);
    float4 a1 = make_float4(0.f, 0.f, 0.f, 0.f);

    int j = beg;
    for (; j + 4 <= end; j += 4) {
        int s0 = __ldg(g_srcs + j + 0);
        int s1 = __ldg(g_srcs + j + 1);
        int s2 = __ldg(g_srcs + j + 2);
        int s3 = __ldg(g_srcs + j + 3);
        uint2 v0 = __ldg(hb + (size_t)s0 * C4 + lane);
        uint2 v1 = __ldg(hb + (size_t)s1 * C4 + lane);
        uint2 v2 = __ldg(hb + (size_t)s2 * C4 + lane);
        uint2 v3 = __ldg(hb + (size_t)s3 * C4 + lane);
        addbf(a0, v0); addbf(a1, v1); addbf(a0, v2); addbf(a1, v3);
    }
    for (; j < end; j++) {
        int s0 = __ldg(g_srcs + j);
        uint2 v0 = __ldg(hb + (size_t)s0 * C4 + lane);
        addbf(a0, v0);
    }

    float inv = 1.0f / fmaxf((float)(end - beg), 1.0f);
    float4 m;
    m.x = (a0.x + a1.x) * inv;
    m.y = (a0.y + a1.y) * inv;
    m.z = (a0.z + a1.z) * inv;
    m.w = (a0.w + a1.w) * inv;
    g_mean[(size_t)node * C4 + lane] = m;
}

// ================= fused SAGE layer GEMM (tf32 mma, m32n64 warp tile) =================
// out = relu( [mean | x] @ [Wl ; Wr] + b ),  K = 256 (8 chunks of 32)
__global__ void __launch_bounds__(256, 2)
k_layer_mma(const float* __restrict__ Xext,   // null -> g_h1
            const float* __restrict__ Wl,
            const float* __restrict__ Wr,
            const float* __restrict__ bias,
            int out_sel) {                    // 0 -> h1 (+bf16 copy), 1 -> h2
    const float* __restrict__ X = Xext ? Xext : (const float*)g_h1;
    float* out = out_sel ? (float*)g_h2 : (float*)g_h1;

    __shared__ float sA [BM * SA_STR];          // [row][k]
    __shared__ float sB2[16 * SB2_STR * 2];     // float2[(ks*4+c)*132+n] = (B[k],B[k+4])

    int tid = threadIdx.x, wid = tid >> 5, lane = tid & 31;
    int rowbase = blockIdx.x * BM;
    int warpm = (wid & 3) * 32;
    int warpn = (wid >> 2) * 64;

    float acc[2][8][4];
    #pragma unroll
    for (int mt = 0; mt < 2; mt++)
        #pragma unroll
        for (int nt = 0; nt < 8; nt++)
            { acc[mt][nt][0]=0.f; acc[mt][nt][1]=0.f; acc[mt][nt][2]=0.f; acc[mt][nt][3]=0.f; }

    for (int kc = 0; kc < 8; kc++) {
        bool meanpart = kc < 4;
        // ---- A tile
        #pragma unroll
        for (int it = 0; it < 4; it++) {
            int f4 = tid + it * 256;
            int r  = f4 >> 3;
            int q  = f4 & 7;
            int row = rowbase + r;
            float4 v = make_float4(0.f, 0.f, 0.f, 0.f);
            if (row < N_NODES) {
                if (meanpart) v = g_mean[(size_t)row * C4 + kc * 8 + q];
                else          v = ((const float4*)X)[(size_t)row * C4 + (kc - 4) * 8 + q];
            }
            float* d = sA + r * SA_STR + q * 4;
            d[0] = to_tf32(v.x); d[1] = to_tf32(v.y);
            d[2] = to_tf32(v.z); d[3] = to_tf32(v.w);
        }
        // ---- B tile (paired layout)
        const float* Wsrc = meanpart ? Wl : Wr;
        int kw0 = (meanpart ? kc : kc - 4) * KC;
        #pragma unroll
        for (int it = 0; it < 4; it++) {
            int f4 = tid + it * 256;
            int k  = f4 >> 5;                  // 0..31
            int q  = f4 & 31;
            int n0 = q * 4;
            int ks = k >> 3, c = k & 3, hi = (k >> 2) & 1;
            float4 v = __ldg((const float4*)(Wsrc + (size_t)(kw0 + k) * C) + n0 / 4);
            float* d = sB2 + ((ks * 4 + c) * SB2_STR) * 2 + hi;
            d[(n0 + 0) * 2] = to_tf32(v.x);
            d[(n0 + 1) * 2] = to_tf32(v.y);
            d[(n0 + 2) * 2] = to_tf32(v.z);
            d[(n0 + 3) * 2] = to_tf32(v.w);
        }
        __syncthreads();

        #pragma unroll
        for (int ks = 0; ks < 4; ks++) {
            int k0 = ks * 8;
            uint32_t A[2][4];
            #pragma unroll
            for (int mt = 0; mt < 2; mt++) {
                int ar = warpm + mt * 16 + (lane >> 2);
                int ac = k0 + (lane & 3);
                A[mt][0] = __float_as_uint(sA[ar * SA_STR + ac]);
                A[mt][1] = __float_as_uint(sA[(ar + 8) * SA_STR + ac]);
                A[mt][2] = __float_as_uint(sA[ar * SA_STR + ac + 4]);
                A[mt][3] = __float_as_uint(sA[(ar + 8) * SA_STR + ac + 4]);
            }
            const float2* bp = (const float2*)sB2;
            #pragma unroll
            for (int nt = 0; nt < 8; nt++) {
                float2 b = bp[(ks * 4 + (lane & 3)) * SB2_STR + warpn + nt * 8 + (lane >> 2)];
                uint32_t b0 = __float_as_uint(b.x);
                uint32_t b1 = __float_as_uint(b.y);
                mma8(acc[0][nt], A[0][0], A[0][1], A[0][2], A[0][3], b0, b1);
                mma8(acc[1][nt], A[1][0], A[1][1], A[1][2], A[1][3], b0, b1);
            }
        }
        __syncthreads();
    }

    // ---- epilogue
    #pragma unroll
    for (int mt = 0; mt < 2; mt++) {
        int rA = rowbase + warpm + mt * 16 + (lane >> 2);
        int rB = rA + 8;
        #pragma unroll
        for (int nt = 0; nt < 8; nt++) {
            int cbase = warpn + nt * 8 + (lane & 3) * 2;
            float2 b2 = __ldg((const float2*)(bias + cbase));
            if (rA < N_NODES) {
                float2 o; o.x = fmaxf(acc[mt][nt][0] + b2.x, 0.f);
                          o.y = fmaxf(acc[mt][nt][1] + b2.y, 0.f);
                *(float2*)(out + (size_t)rA * C + cbase) = o;
                if (out_sel == 0)
                    ((unsigned*)g_h1b)[(size_t)rA * 64 + cbase / 2] = f2bf(o.x, o.y);
            }
            if (rB < N_NODES) {
                float2 o; o.x = fmaxf(acc[mt][nt][2] + b2.x, 0.f);
                          o.y = fmaxf(acc[mt][nt][3] + b2.y, 0.f);
                *(float2*)(out + (size_t)rB * C + cbase) = o;
                if (out_sel == 0)
                    ((unsigned*)g_h1b)[(size_t)rB * 64 + cbase / 2] = f2bf(o.x, o.y);
            }
        }
    }
}

// ================= decoder + residual (tf32 mma, m32n64), K = 128 =================
__global__ void __launch_bounds__(256, 2)
k_dec_mma(const float* __restrict__ x,
          const float* __restrict__ Wd,
          const float* __restrict__ bd,
          const float* __restrict__ alphaPtr,
          float* __restrict__ out) {
    __shared__ float sA [BM * SA_STR];
    __shared__ float sB2[16 * SB2_STR * 2];

    int tid = threadIdx.x, wid = tid >> 5, lane = tid & 31;
    int rowbase = blockIdx.x * BM;
    int warpm = (wid & 3) * 32;
    int warpn = (wid >> 2) * 64;
    float alpha = __ldg(alphaPtr);
    float beta  = 1.0f - alpha;

    float acc[2][8][4];
    #pragma unroll
    for (int mt = 0; mt < 2; mt++)
        #pragma unroll
        for (int nt = 0; nt < 8; nt++)
            { acc[mt][nt][0]=0.f; acc[mt][nt][1]=0.f; acc[mt][nt][2]=0.f; acc[mt][nt][3]=0.f; }

    for (int kc = 0; kc < 4; kc++) {
        #pragma unroll
        for (int it = 0; it < 4; it++) {
            int f4 = tid + it * 256;
            int r  = f4 >> 3;
            int q  = f4 & 7;
            int row = rowbase + r;
            float4 v = make_float4(0.f, 0.f, 0.f, 0.f);
            if (row < N_NODES)
                v = g_h2[(size_t)row * C4 + kc * 8 + q];
            float* d = sA + r * SA_STR + q * 4;
            d[0] = to_tf32(v.x); d[1] = to_tf32(v.y);
            d[2] = to_tf32(v.z); d[3] = to_tf32(v.w);
        }
        #pragma unroll
        for (int it = 0; it < 4; it++) {
            int f4 = tid + it * 256;
            int k  = f4 >> 5;
            int q  = f4 & 31;
            int n0 = q * 4;
            int ks = k >> 3, c = k & 3, hi = (k >> 2) & 1;
            float4 v = __ldg((const float4*)(Wd + (size_t)(kc * KC + k) * C) + q);
            float* d = sB2 + ((ks * 4 + c) * SB2_STR) * 2 + hi;
            d[(n0 + 0) * 2] = to_tf32(v.x);
            d[(n0 + 1) * 2] = to_tf32(v.y);
            d[(n0 + 2) * 2] = to_tf32(v.z);
            d[(n0 + 3) * 2] = to_tf32(v.w);
        }
        __syncthreads();

        #pragma unroll
        for (int ks = 0; ks < 4; ks++) {
            int k0 = ks * 8;
            uint32_t A[2][4];
            #pragma unroll
            for (int mt = 0; mt < 2; mt++) {
                int ar = warpm + mt * 16 + (lane >> 2);
                int ac = k0 + (lane & 3);
                A[mt][0] = __float_as_uint(sA[ar * SA_STR + ac]);
                A[mt][1] = __float_as_uint(sA[(ar + 8) * SA_STR + ac]);
                A[mt][2] = __float_as_uint(sA[ar * SA_STR + ac + 4]);
                A[mt][3] = __float_as_uint(sA[(ar + 8) * SA_STR + ac + 4]);
            }
            const float2* bp = (const float2*)sB2;
            #pragma unroll
            for (int nt = 0; nt < 8; nt++) {
                float2 b = bp[(ks * 4 + (lane & 3)) * SB2_STR + warpn + nt * 8 + (lane >> 2)];
                uint32_t b0 = __float_as_uint(b.x);
                uint32_t b1 = __float_as_uint(b.y);
                mma8(acc[0][nt], A[0][0], A[0][1], A[0][2], A[0][3], b0, b1);
                mma8(acc[1][nt], A[1][0], A[1][1], A[1][2], A[1][3], b0, b1);
            }
        }
        __syncthreads();
    }

    #pragma unroll
    for (int mt = 0; mt < 2; mt++) {
        int rA = rowbase + warpm + mt * 16 + (lane >> 2);
        int rB = rA + 8;
        #pragma unroll
        for (int nt = 0; nt < 8; nt++) {
            int cbase = warpn + nt * 8 + (lane & 3) * 2;
            float2 b2 = __ldg((const float2*)(bd + cbase));
            if (rA < N_NODES) {
                float2 xv = __ldg((const float2*)(x + (size_t)rA * C + cbase));
                float2 o; o.x = alpha * (acc[mt][nt][0] + b2.x) + beta * xv.x;
                          o.y = alpha * (acc[mt][nt][1] + b2.y) + beta * xv.y;
                *(float2*)(out + (size_t)rA * C + cbase) = o;
            }
            if (rB < N_NODES) {
                float2 xv = __ldg((const float2*)(x + (size_t)rB * C + cbase));
                float2 o; o.x = alpha * (acc[mt][nt][2] + b2.x) + beta * xv.x;
                          o.y = alpha * (acc[mt][nt][3] + b2.y) + beta * xv.y;
                *(float2*)(out + (size_t)rB * C + cbase) = o;
            }
        }
    }
}

// ================= launch =================
extern "C" void kernel_launch(void* const* d_in, const int* in_sizes, int n_in,
                              void* d_out, int out_size) {
    const float4* x   = (const float4*)d_in[0];
    const int*    ei  = (const int*)  d_in[1];
    const float*  W1l = (const float*)d_in[2];
    const float*  b1  = (const float*)d_in[3];
    const float*  W1r = (const float*)d_in[4];
    const float*  W2l = (const float*)d_in[5];
    const float*  b2  = (const float*)d_in[6];
    const float*  W2r = (const float*)d_in[7];
    const float*  Wd  = (const float*)d_in[8];
    const float*  bd  = (const float*)d_in[9];
    const float*  alp = (const float*)d_in[10];
    float* out = (float*)d_out;

    const int edgeBlocks = (N_EDGES + 255) / 256;
    const int cvtBlocks  = (N_NODES * C4 + 255) / 256;
    const int aggBlocks  = (N_NODES * 32 + 255) / 256;
    const int mmaBlocks  = (N_NODES + BM - 1) / BM;

    // x -> bf16 and CSR build
    k_cvt_x<<<cvtBlocks, 256>>>(x);
    k_csr_init<<<256, 256>>>();
    k_hist<<<edgeBlocks, 256>>>(ei);
    k_scan<<<1, 1024>>>();
    k_fill<<<edgeBlocks, 256>>>(ei);

    // Layer 1
    k_agg<<<aggBlocks, 256>>>(1);
    k_layer_mma<<<mmaBlocks, 256>>>((const float*)x, W1l, W1r, b1, /*out=h1*/0);

    // Layer 2
    k_agg<<<aggBlocks, 256>>>(0);
    k_layer_mma<<<mmaBlocks, 256>>>(nullptr, W2l, W2r, b2, /*out=h2*/1);

    // Decoder + residual
    k_dec_mma<<<mmaBlocks, 256>>>((const float*)x, Wd, bd, alp, out);
}

// round 9
// speedup vs baseline: 1.1923x; 1.1923x over previous
#include <cuda_runtime.h>
#include <cstdint>

#define N_NODES 100000
#define N_EDGES 1600000
#define C       128
#define C4      32
#define BM      128
#define KC      32
#define SA_STR  36
#define SB_STR  136

#define SCAN_EPB 2048                 // elements per scan block
#define SCAN_NB  ((N_NODES + SCAN_EPB - 1) / SCAN_EPB)   // 49

// ---------------- scratch ----------------
__device__ float4 g_mean[(size_t)N_NODES * C4];
__device__ float4 g_h1 [(size_t)N_NODES * C4];
__device__ float4 g_h2 [(size_t)N_NODES * C4];
__device__ int    g_deg [N_NODES];
__device__ int    g_cur [N_NODES];
__device__ int    g_off [N_NODES + 1];
__device__ int    g_srcs[N_EDGES];
__device__ int    g_bsum[SCAN_NB];

// ---------------- helpers ----------------
__device__ __forceinline__ float to_tf32(float x) {
    uint32_t u;
    asm("cvt.rna.tf32.f32 %0, %1;" : "=r"(u) : "f"(x));
    return __uint_as_float(u);
}
__device__ __forceinline__ void mma8(float* c,
                                     uint32_t a0, uint32_t a1, uint32_t a2, uint32_t a3,
                                     uint32_t b0, uint32_t b1) {
    asm volatile("mma.sync.aligned.m16n8k8.row.col.f32.tf32.tf32.f32 "
                 "{%0,%1,%2,%3}, {%4,%5,%6,%7}, {%8,%9}, {%0,%1,%2,%3};"
                 : "+f"(c[0]), "+f"(c[1]), "+f"(c[2]), "+f"(c[3])
                 : "r"(a0), "r"(a1), "r"(a2), "r"(a3), "r"(b0), "r"(b1));
}

// ================= CSR build =================
__global__ void k_csr_init() {
    int i = blockIdx.x * blockDim.x + threadIdx.x;
    int stride = gridDim.x * blockDim.x;
    for (int j = i; j < N_NODES; j += stride) { g_deg[j] = 0; g_cur[j] = 0; }
}

__global__ void k_hist(const int* __restrict__ ei) {
    int e = blockIdx.x * blockDim.x + threadIdx.x;
    if (e >= N_EDGES) return;
    atomicAdd(g_deg + ei[N_EDGES + e], 1);
}

// ---- scan stage 1: per-block inclusive prefix into g_off[i+1], totals to g_bsum
__global__ void __launch_bounds__(256)
k_scan1() {
    __shared__ int s_warp[8];
    int b = blockIdx.x, tid = threadIdx.x, lane = tid & 31, wid = tid >> 5;
    int base = b * SCAN_EPB + tid * 8;

    int v[8]; int tot = 0;
    #pragma unroll
    for (int u = 0; u < 8; u++) {
        int i = base + u;
        v[u] = (i < N_NODES) ? g_deg[i] : 0;
        tot += v[u];
    }
    // warp inclusive scan of thread totals
    int s = tot;
    #pragma unroll
    for (int o = 1; o < 32; o <<= 1) {
        int t = __shfl_up_sync(0xffffffffu, s, o);
        if (lane >= o) s += t;
    }
    if (lane == 31) s_warp[wid] = s;
    __syncthreads();
    if (wid == 0) {
        int w = (lane < 8) ? s_warp[lane] : 0;
        #pragma unroll
        for (int o = 1; o < 8; o <<= 1) {
            int t = __shfl_up_sync(0xffffffffu, w, o);
            if (lane >= o) w += t;
        }
        if (lane < 8) s_warp[lane] = w;
    }
    __syncthreads();

    int excl = (wid ? s_warp[wid - 1] : 0) + s - tot;   // thread-exclusive base
    int run = excl;
    #pragma unroll
    for (int u = 0; u < 8; u++) {
        int i = base + u;
        run += v[u];
        if (i < N_NODES) g_off[i + 1] = run;
    }
    if (tid == 0) g_bsum[b] = s_warp[7];
}

// ---- scan stage 2: each block reduces preceding block totals, adds offset
__global__ void __launch_bounds__(256)
k_scan2() {
    __shared__ int s_off;
    int b = blockIdx.x, tid = threadIdx.x, lane = tid & 31;
    if (tid < 32) {
        int acc = 0;
        if (lane      < b) acc += g_bsum[lane];
        if (lane + 32 < b) acc += g_bsum[lane + 32];
        #pragma unroll
        for (int o = 16; o > 0; o >>= 1)
            acc += __shfl_down_sync(0xffffffffu, acc, o);
        if (lane == 0) s_off = acc;
    }
    __syncthreads();
    int off = s_off;
    if (off != 0) {
        int base = b * SCAN_EPB + tid * 8;
        #pragma unroll
        for (int u = 0; u < 8; u++) {
            int i = base + u;
            if (i < N_NODES) g_off[i + 1] += off;
        }
    }
    if (b == 0 && tid == 0) g_off[0] = 0;
}

__global__ void k_fill(const int* __restrict__ ei) {
    int e = blockIdx.x * blockDim.x + threadIdx.x;
    if (e >= N_EDGES) return;
    int srcv = ei[e];
    int d    = ei[N_EDGES + e];
    int pos  = atomicAdd(g_cur + d, 1);
    g_srcs[g_off[d] + pos] = srcv;
}

// ================= aggregation (gather, shfl-free broadcast) =================
__global__ void __launch_bounds__(256)
k_agg(const float4* __restrict__ h_ext) {   // null -> g_h1
    const float4* __restrict__ h = h_ext ? h_ext : (const float4*)g_h1;
    int node = (blockIdx.x * blockDim.x + threadIdx.x) >> 5;
    if (node >= N_NODES) return;
    int lane = threadIdx.x & 31;

    int beg = __ldg(g_off + node);
    int end = __ldg(g_off + node + 1);

    float4 a0 = make_float4(0.f, 0.f, 0.f, 0.f);
    float4 a1 = make_float4(0.f, 0.f, 0.f, 0.f);

    int j = beg;
    for (; j + 4 <= end; j += 4) {
        int s0 = __ldg(g_srcs + j + 0);
        int s1 = __ldg(g_srcs + j + 1);
        int s2 = __ldg(g_srcs + j + 2);
        int s3 = __ldg(g_srcs + j + 3);
        float4 v0 = __ldg(h + (size_t)s0 * C4 + lane);
        float4 v1 = __ldg(h + (size_t)s1 * C4 + lane);
        float4 v2 = __ldg(h + (size_t)s2 * C4 + lane);
        float4 v3 = __ldg(h + (size_t)s3 * C4 + lane);
        a0.x += v0.x; a0.y += v0.y; a0.z += v0.z; a0.w += v0.w;
        a1.x += v1.x; a1.y += v1.y; a1.z += v1.z; a1.w += v1.w;
        a0.x += v2.x; a0.y += v2.y; a0.z += v2.z; a0.w += v2.w;
        a1.x += v3.x; a1.y += v3.y; a1.z += v3.z; a1.w += v3.w;
    }
    for (; j < end; j++) {
        int s0 = __ldg(g_srcs + j);
        float4 v0 = __ldg(h + (size_t)s0 * C4 + lane);
        a0.x += v0.x; a0.y += v0.y; a0.z += v0.z; a0.w += v0.w;
    }

    float inv = 1.0f / fmaxf((float)(end - beg), 1.0f);
    float4 m;
    m.x = (a0.x + a1.x) * inv;
    m.y = (a0.y + a1.y) * inv;
    m.z = (a0.z + a1.z) * inv;
    m.w = (a0.w + a1.w) * inv;
    g_mean[(size_t)node * C4 + lane] = m;
}

// ================= fused SAGE layer GEMM (tf32 mma) =================
// out = relu( [mean | x] @ [Wl ; Wr] + b ),  K = 256 (8 chunks of 32)
__global__ void __launch_bounds__(256, 2)
k_layer_mma(const float* __restrict__ Xext,   // null -> g_h1
            const float* __restrict__ Wl,
            const float* __restrict__ Wr,
            const float* __restrict__ bias,
            int out_sel) {
    const float* __restrict__ X = Xext ? Xext : (const float*)g_h1;
    float* out = out_sel ? (float*)g_h2 : (float*)g_h1;

    __shared__ float sA[BM * SA_STR];
    __shared__ float sB[KC * SB_STR];

    int tid = threadIdx.x, wid = tid >> 5, lane = tid & 31;
    int rowbase = blockIdx.x * BM;

    float acc[16][4];
    #pragma unroll
    for (int t = 0; t < 16; t++) { acc[t][0]=0.f; acc[t][1]=0.f; acc[t][2]=0.f; acc[t][3]=0.f; }

    for (int kc = 0; kc < 8; kc++) {
        bool meanpart = kc < 4;
        #pragma unroll
        for (int it = 0; it < 4; it++) {
            int f4 = tid + it * 256;
            int r  = f4 >> 3;
            int q  = f4 & 7;
            int row = rowbase + r;
            float4 v = make_float4(0.f, 0.f, 0.f, 0.f);
            if (row < N_NODES) {
                if (meanpart) v = g_mean[(size_t)row * C4 + kc * 8 + q];
                else          v = ((const float4*)X)[(size_t)row * C4 + (kc - 4) * 8 + q];
            }
            float* d = sA + r * SA_STR + q * 4;
            d[0] = to_tf32(v.x); d[1] = to_tf32(v.y);
            d[2] = to_tf32(v.z); d[3] = to_tf32(v.w);
        }
        const float* Wsrc = meanpart ? Wl : Wr;
        int kw0 = (meanpart ? kc : kc - 4) * KC;
        #pragma unroll
        for (int it = 0; it < 4; it++) {
            int f4 = tid + it * 256;
            int k  = f4 >> 5;
            int q  = f4 & 31;
            float4 v = __ldg((const float4*)(Wsrc + (size_t)(kw0 + k) * C) + q);
            float* d = sB + k * SB_STR + q * 4;
            d[0] = to_tf32(v.x); d[1] = to_tf32(v.y);
            d[2] = to_tf32(v.z); d[3] = to_tf32(v.w);
        }
        __syncthreads();

        int r0 = wid * 16;
        #pragma unroll
        for (int ks = 0; ks < 4; ks++) {
            int k0 = ks * 8;
            int ar = r0 + (lane >> 2);
            int ac = k0 + (lane & 3);
            uint32_t a0 = __float_as_uint(sA[ar * SA_STR + ac]);
            uint32_t a1 = __float_as_uint(sA[(ar + 8) * SA_STR + ac]);
            uint32_t a2 = __float_as_uint(sA[ar * SA_STR + ac + 4]);
            uint32_t a3 = __float_as_uint(sA[(ar + 8) * SA_STR + ac + 4]);
            int bk = k0 + (lane & 3);
            int bn = lane >> 2;
            #pragma unroll
            for (int t = 0; t < 16; t++) {
                uint32_t b0 = __float_as_uint(sB[bk * SB_STR + t * 8 + bn]);
                uint32_t b1 = __float_as_uint(sB[(bk + 4) * SB_STR + t * 8 + bn]);
                mma8(acc[t], a0, a1, a2, a3, b0, b1);
            }
        }
        __syncthreads();
    }

    int rA = rowbase + wid * 16 + (lane >> 2);
    int rB = rA + 8;
    #pragma unroll
    for (int t = 0; t < 16; t++) {
        int cbase = t * 8 + (lane & 3) * 2;
        float2 b2 = __ldg((const float2*)(bias + cbase));
        if (rA < N_NODES) {
            float2 o; o.x = fmaxf(acc[t][0] + b2.x, 0.f);
                      o.y = fmaxf(acc[t][1] + b2.y, 0.f);
            *(float2*)(out + (size_t)rA * C + cbase) = o;
        }
        if (rB < N_NODES) {
            float2 o; o.x = fmaxf(acc[t][2] + b2.x, 0.f);
                      o.y = fmaxf(acc[t][3] + b2.y, 0.f);
            *(float2*)(out + (size_t)rB * C + cbase) = o;
        }
    }
}

// ================= decoder + residual (tf32 mma), K = 128 =================
__global__ void __launch_bounds__(256, 2)
k_dec_mma(const float* __restrict__ x,
          const float* __restrict__ Wd,
          const float* __restrict__ bd,
          const float* __restrict__ alphaPtr,
          float* __restrict__ out) {
    __shared__ float sA[BM * SA_STR];
    __shared__ float sB[KC * SB_STR];

    int tid = threadIdx.x, wid = tid >> 5, lane = tid & 31;
    int rowbase = blockIdx.x * BM;
    float alpha = __ldg(alphaPtr);
    float beta  = 1.0f - alpha;

    float acc[16][4];
    #pragma unroll
    for (int t = 0; t < 16; t++) { acc[t][0]=0.f; acc[t][1]=0.f; acc[t][2]=0.f; acc[t][3]=0.f; }

    for (int kc = 0; kc < 4; kc++) {
        #pragma unroll
        for (int it = 0; it < 4; it++) {
            int f4 = tid + it * 256;
            int r  = f4 >> 3;
            int q  = f4 & 7;
            int row = rowbase + r;
            float4 v = make_float4(0.f, 0.f, 0.f, 0.f);
            if (row < N_NODES)
                v = g_h2[(size_t)row * C4 + kc * 8 + q];
            float* d = sA + r * SA_STR + q * 4;
            d[0] = to_tf32(v.x); d[1] = to_tf32(v.y);
            d[2] = to_tf32(v.z); d[3] = to_tf32(v.w);
        }
        #pragma unroll
        for (int it = 0; it < 4; it++) {
            int f4 = tid + it * 256;
            int k  = f4 >> 5;
            int q  = f4 & 31;
            float4 v = __ldg((const float4*)(Wd + (size_t)(kc * KC + k) * C) + q);
            float* d = sB + k * SB_STR + q * 4;
            d[0] = to_tf32(v.x); d[1] = to_tf32(v.y);
            d[2] = to_tf32(v.z); d[3] = to_tf32(v.w);
        }
        __syncthreads();

        int r0 = wid * 16;
        #pragma unroll
        for (int ks = 0; ks < 4; ks++) {
            int k0 = ks * 8;
            int ar = r0 + (lane >> 2);
            int ac = k0 + (lane & 3);
            uint32_t a0 = __float_as_uint(sA[ar * SA_STR + ac]);
            uint32_t a1 = __float_as_uint(sA[(ar + 8) * SA_STR + ac]);
            uint32_t a2 = __float_as_uint(sA[ar * SA_STR + ac + 4]);
            uint32_t a3 = __float_as_uint(sA[(ar + 8) * SA_STR + ac + 4]);
            int bk = k0 + (lane & 3);
            int bn = lane >> 2;
            #pragma unroll
            for (int t = 0; t < 16; t++) {
                uint32_t b0 = __float_as_uint(sB[bk * SB_STR + t * 8 + bn]);
                uint32_t b1 = __float_as_uint(sB[(bk + 4) * SB_STR + t * 8 + bn]);
                mma8(acc[t], a0, a1, a2, a3, b0, b1);
            }
        }
        __syncthreads();
    }

    int rA = rowbase + wid * 16 + (lane >> 2);
    int rB = rA + 8;
    #pragma unroll
    for (int t = 0; t < 16; t++) {
        int cbase = t * 8 + (lane & 3) * 2;
        float2 b2 = __ldg((const float2*)(bd + cbase));
        if (rA < N_NODES) {
            float2 xv = __ldg((const float2*)(x + (size_t)rA * C + cbase));
            float2 o; o.x = alpha * (acc[t][0] + b2.x) + beta * xv.x;
                      o.y = alpha * (acc[t][1] + b2.y) + beta * xv.y;
            *(float2*)(out + (size_t)rA * C + cbase) = o;
        }
        if (rB < N_NODES) {
            float2 xv = __ldg((const float2*)(x + (size_t)rB * C + cbase));
            float2 o; o.x = alpha * (acc[t][2] + b2.x) + beta * xv.x;
                      o.y = alpha * (acc[t][3] + b2.y) + beta * xv.y;
            *(float2*)(out + (size_t)rB * C + cbase) = o;
        }
    }
}

// ================= launch =================
extern "C" void kernel_launch(void* const* d_in, const int* in_sizes, int n_in,
                              void* d_out, int out_size) {
    const float4* x   = (const float4*)d_in[0];
    const int*    ei  = (const int*)  d_in[1];
    const float*  W1l = (const float*)d_in[2];
    const float*  b1  = (const float*)d_in[3];
    const float*  W1r = (const float*)d_in[4];
    const float*  W2l = (const float*)d_in[5];
    const float*  b2  = (const float*)d_in[6];
    const float*  W2r = (const float*)d_in[7];
    const float*  Wd  = (const float*)d_in[8];
    const float*  bd  = (const float*)d_in[9];
    const float*  alp = (const float*)d_in[10];
    float* out = (float*)d_out;

    const int edgeBlocks = (N_EDGES + 255) / 256;
    const int aggBlocks  = (N_NODES * 32 + 255) / 256;
    const int mmaBlocks  = (N_NODES + BM - 1) / BM;

    // CSR build (parallel scan)
    k_csr_init<<<256, 256>>>();
    k_hist<<<edgeBlocks, 256>>>(ei);
    k_scan1<<<SCAN_NB, 256>>>();
    k_scan2<<<SCAN_NB, 256>>>();
    k_fill<<<edgeBlocks, 256>>>(ei);

    // Layer 1
    k_agg<<<aggBlocks, 256>>>(x);
    k_layer_mma<<<mmaBlocks, 256>>>((const float*)x, W1l, W1r, b1, /*out=h1*/0);

    // Layer 2
    k_agg<<<aggBlocks, 256>>>(nullptr);
    k_layer_mma<<<mmaBlocks, 256>>>(nullptr, W2l, W2r, b2, /*out=h2*/1);

    // Decoder + residual
    k_dec_mma<<<mmaBlocks, 256>>>((const float*)x, Wd, bd, alp, out);
}

// round 10
// speedup vs baseline: 1.1958x; 1.0030x over previous
#include <cuda_runtime.h>
#include <cuda_bf16.h>
#include <cstdint>

#define N_NODES 100000
#define N_EDGES 1600000
#define C       128
#define C4      32
#define BM      128
#define KC      32
#define SA_STR  36
#define SB_STR  136

#define SCAN_EPB 2048
#define SCAN_NB  ((N_NODES + SCAN_EPB - 1) / SCAN_EPB)   // 49

// ---------------- scratch ----------------
__device__ float4 g_mean[(size_t)N_NODES * C4];
__device__ float4 g_h1 [(size_t)N_NODES * C4];
__device__ float4 g_h2 [(size_t)N_NODES * C4];
__device__ uint2  g_xb [(size_t)N_NODES * C4];   // bf16 x   (gather operand)
__device__ uint2  g_h1b[(size_t)N_NODES * C4];   // bf16 h1  (gather operand)
__device__ int    g_deg [N_NODES];
__device__ int    g_cur [N_NODES];
__device__ int    g_off [N_NODES + 1];
__device__ int    g_srcs[N_EDGES];
__device__ int    g_bsum[SCAN_NB];

// ---------------- helpers ----------------
__device__ __forceinline__ float to_tf32(float x) {
    uint32_t u;
    asm("cvt.rna.tf32.f32 %0, %1;" : "=r"(u) : "f"(x));
    return __uint_as_float(u);
}
__device__ __forceinline__ void mma8(float* c,
                                     uint32_t a0, uint32_t a1, uint32_t a2, uint32_t a3,
                                     uint32_t b0, uint32_t b1) {
    asm volatile("mma.sync.aligned.m16n8k8.row.col.f32.tf32.tf32.f32 "
                 "{%0,%1,%2,%3}, {%4,%5,%6,%7}, {%8,%9}, {%0,%1,%2,%3};"
                 : "+f"(c[0]), "+f"(c[1]), "+f"(c[2]), "+f"(c[3])
                 : "r"(a0), "r"(a1), "r"(a2), "r"(a3), "r"(b0), "r"(b1));
}
__device__ __forceinline__ float2 bf2f(unsigned u) {
    __nv_bfloat162 b = *reinterpret_cast<__nv_bfloat162*>(&u);
    return __bfloat1622float2(b);
}
__device__ __forceinline__ unsigned f2bf(float a, float b) {
    __nv_bfloat162 v = __float22bfloat162_rn(make_float2(a, b));
    return *reinterpret_cast<unsigned*>(&v);
}
__device__ __forceinline__ void addbf(float4& a, uint2 v) {
    float2 lo = bf2f(v.x), hi = bf2f(v.y);
    a.x += lo.x; a.y += lo.y; a.z += hi.x; a.w += hi.y;
}

// ================= x -> bf16 =================
__global__ void k_cvt_x(const float4* __restrict__ x) {
    int i = blockIdx.x * blockDim.x + threadIdx.x;
    if (i >= N_NODES * C4) return;
    float4 v = __ldg(x + i);
    g_xb[i] = make_uint2(f2bf(v.x, v.y), f2bf(v.z, v.w));
}

// ================= CSR build =================
__global__ void k_csr_init() {
    int i = blockIdx.x * blockDim.x + threadIdx.x;
    int stride = gridDim.x * blockDim.x;
    for (int j = i; j < N_NODES; j += stride) { g_deg[j] = 0; g_cur[j] = 0; }
}

__global__ void k_hist(const int* __restrict__ ei) {
    int e = blockIdx.x * blockDim.x + threadIdx.x;
    if (e >= N_EDGES) return;
    atomicAdd(g_deg + ei[N_EDGES + e], 1);
}

__global__ void __launch_bounds__(256)
k_scan1() {
    __shared__ int s_warp[8];
    int b = blockIdx.x, tid = threadIdx.x, lane = tid & 31, wid = tid >> 5;
    int base = b * SCAN_EPB + tid * 8;

    int v[8]; int tot = 0;
    #pragma unroll
    for (int u = 0; u < 8; u++) {
        int i = base + u;
        v[u] = (i < N_NODES) ? g_deg[i] : 0;
        tot += v[u];
    }
    int s = tot;
    #pragma unroll
    for (int o = 1; o < 32; o <<= 1) {
        int t = __shfl_up_sync(0xffffffffu, s, o);
        if (lane >= o) s += t;
    }
    if (lane == 31) s_warp[wid] = s;
    __syncthreads();
    if (wid == 0) {
        int w = (lane < 8) ? s_warp[lane] : 0;
        #pragma unroll
        for (int o = 1; o < 8; o <<= 1) {
            int t = __shfl_up_sync(0xffffffffu, w, o);
            if (lane >= o) w += t;
        }
        if (lane < 8) s_warp[lane] = w;
    }
    __syncthreads();

    int excl = (wid ? s_warp[wid - 1] : 0) + s - tot;
    int run = excl;
    #pragma unroll
    for (int u = 0; u < 8; u++) {
        int i = base + u;
        run += v[u];
        if (i < N_NODES) g_off[i + 1] = run;
    }
    if (tid == 0) g_bsum[b] = s_warp[7];
}

__global__ void __launch_bounds__(256)
k_scan2() {
    __shared__ int s_off;
    int b = blockIdx.x, tid = threadIdx.x, lane = tid & 31;
    if (tid < 32) {
        int acc = 0;
        if (lane      < b) acc += g_bsum[lane];
        if (lane + 32 < b) acc += g_bsum[lane + 32];
        #pragma unroll
        for (int o = 16; o > 0; o >>= 1)
            acc += __shfl_down_sync(0xffffffffu, acc, o);
        if (lane == 0) s_off = acc;
    }
    __syncthreads();
    int off = s_off;
    if (off != 0) {
        int base = b * SCAN_EPB + tid * 8;
        #pragma unroll
        for (int u = 0; u < 8; u++) {
            int i = base + u;
            if (i < N_NODES) g_off[i + 1] += off;
        }
    }
    if (b == 0 && tid == 0) g_off[0] = 0;
}

__global__ void k_fill(const int* __restrict__ ei) {
    int e = blockIdx.x * blockDim.x + threadIdx.x;
    if (e >= N_EDGES) return;
    int srcv = ei[e];
    int d    = ei[N_EDGES + e];
    int pos  = atomicAdd(g_cur + d, 1);
    g_srcs[g_off[d] + pos] = srcv;
}

// ================= aggregation (bf16 gather, shfl-free broadcast) =================
__global__ void __launch_bounds__(256)
k_agg(int use_x) {
    const uint2* __restrict__ hb = use_x ? (const uint2*)g_xb : (const uint2*)g_h1b;
    int node = (blockIdx.x * blockDim.x + threadIdx.x) >> 5;
    if (node >= N_NODES) return;
    int lane = threadIdx.x & 31;

    int beg = __ldg(g_off + node);
    int end = __ldg(g_off + node + 1);

    float4 a0 = make_float4(0.f, 0.f, 0.f, 0.f);
    float4 a1 = make_float4(0.f, 0.f, 0.f, 0.f);

    int j = beg;
    for (; j + 4 <= end; j += 4) {
        int s0 = __ldg(g_srcs + j + 0);
        int s1 = __ldg(g_srcs + j + 1);
        int s2 = __ldg(g_srcs + j + 2);
        int s3 = __ldg(g_srcs + j + 3);
        uint2 v0 = __ldg(hb + (size_t)s0 * C4 + lane);
        uint2 v1 = __ldg(hb + (size_t)s1 * C4 + lane);
        uint2 v2 = __ldg(hb + (size_t)s2 * C4 + lane);
        uint2 v3 = __ldg(hb + (size_t)s3 * C4 + lane);
        addbf(a0, v0); addbf(a1, v1); addbf(a0, v2); addbf(a1, v3);
    }
    for (; j < end; j++) {
        int s0 = __ldg(g_srcs + j);
        uint2 v0 = __ldg(hb + (size_t)s0 * C4 + lane);
        addbf(a0, v0);
    }

    float inv = 1.0f / fmaxf((float)(end - beg), 1.0f);
    float4 m;
    m.x = (a0.x + a1.x) * inv;
    m.y = (a0.y + a1.y) * inv;
    m.z = (a0.z + a1.z) * inv;
    m.w = (a0.w + a1.w) * inv;
    g_mean[(size_t)node * C4 + lane] = m;
}

// ================= fused SAGE layer GEMM (tf32 mma) =================
// out = relu( [mean | x] @ [Wl ; Wr] + b ),  K = 256 (8 chunks of 32)
__global__ void __launch_bounds__(256, 2)
k_layer_mma(const float* __restrict__ Xext,   // null -> g_h1
            const float* __restrict__ Wl,
            const float* __restrict__ Wr,
            const float* __restrict__ bias,
            int out_sel) {                    // 0 -> h1 (+bf16 copy), 1 -> h2
    const float* __restrict__ X = Xext ? Xext : (const float*)g_h1;
    float* out = out_sel ? (float*)g_h2 : (float*)g_h1;

    __shared__ float sA[BM * SA_STR];
    __shared__ float sB[KC * SB_STR];

    int tid = threadIdx.x, wid = tid >> 5, lane = tid & 31;
    int rowbase = blockIdx.x * BM;

    float acc[16][4];
    #pragma unroll
    for (int t = 0; t < 16; t++) { acc[t][0]=0.f; acc[t][1]=0.f; acc[t][2]=0.f; acc[t][3]=0.f; }

    for (int kc = 0; kc < 8; kc++) {
        bool meanpart = kc < 4;
        #pragma unroll
        for (int it = 0; it < 4; it++) {
            int f4 = tid + it * 256;
            int r  = f4 >> 3;
            int q  = f4 & 7;
            int row = rowbase + r;
            float4 v = make_float4(0.f, 0.f, 0.f, 0.f);
            if (row < N_NODES) {
                if (meanpart) v = g_mean[(size_t)row * C4 + kc * 8 + q];
                else          v = ((const float4*)X)[(size_t)row * C4 + (kc - 4) * 8 + q];
            }
            float* d = sA + r * SA_STR + q * 4;
            d[0] = to_tf32(v.x); d[1] = to_tf32(v.y);
            d[2] = to_tf32(v.z); d[3] = to_tf32(v.w);
        }
        const float* Wsrc = meanpart ? Wl : Wr;
        int kw0 = (meanpart ? kc : kc - 4) * KC;
        #pragma unroll
        for (int it = 0; it < 4; it++) {
            int f4 = tid + it * 256;
            int k  = f4 >> 5;
            int q  = f4 & 31;
            float4 v = __ldg((const float4*)(Wsrc + (size_t)(kw0 + k) * C) + q);
            float* d = sB + k * SB_STR + q * 4;
            d[0] = to_tf32(v.x); d[1] = to_tf32(v.y);
            d[2] = to_tf32(v.z); d[3] = to_tf32(v.w);
        }
        __syncthreads();

        int r0 = wid * 16;
        #pragma unroll
        for (int ks = 0; ks < 4; ks++) {
            int k0 = ks * 8;
            int ar = r0 + (lane >> 2);
            int ac = k0 + (lane & 3);
            uint32_t a0 = __float_as_uint(sA[ar * SA_STR + ac]);
            uint32_t a1 = __float_as_uint(sA[(ar + 8) * SA_STR + ac]);
            uint32_t a2 = __float_as_uint(sA[ar * SA_STR + ac + 4]);
            uint32_t a3 = __float_as_uint(sA[(ar + 8) * SA_STR + ac + 4]);
            int bk = k0 + (lane & 3);
            int bn = lane >> 2;
            #pragma unroll
            for (int t = 0; t < 16; t++) {
                uint32_t b0 = __float_as_uint(sB[bk * SB_STR + t * 8 + bn]);
                uint32_t b1 = __float_as_uint(sB[(bk + 4) * SB_STR + t * 8 + bn]);
                mma8(acc[t], a0, a1, a2, a3, b0, b1);
            }
        }
        __syncthreads();
    }

    int rA = rowbase + wid * 16 + (lane >> 2);
    int rB = rA + 8;
    #pragma unroll
    for (int t = 0; t < 16; t++) {
        int cbase = t * 8 + (lane & 3) * 2;
        float2 b2 = __ldg((const float2*)(bias + cbase));
        if (rA < N_NODES) {
            float2 o; o.x = fmaxf(acc[t][0] + b2.x, 0.f);
                      o.y = fmaxf(acc[t][1] + b2.y, 0.f);
            *(float2*)(out + (size_t)rA * C + cbase) = o;
            if (out_sel == 0)
                ((unsigned*)g_h1b)[(size_t)rA * 64 + (cbase >> 1)] = f2bf(o.x, o.y);
        }
        if (rB < N_NODES) {
            float2 o; o.x = fmaxf(acc[t][2] + b2.x, 0.f);
                      o.y = fmaxf(acc[t][3] + b2.y, 0.f);
            *(float2*)(out + (size_t)rB * C + cbase) = o;
            if (out_sel == 0)
                ((unsigned*)g_h1b)[(size_t)rB * 64 + (cbase >> 1)] = f2bf(o.x, o.y);
        }
    }
}

// ================= decoder + residual (tf32 mma), K = 128 =================
__global__ void __launch_bounds__(256, 2)
k_dec_mma(const float* __restrict__ x,
          const float* __restrict__ Wd,
          const float* __restrict__ bd,
          const float* __restrict__ alphaPtr,
          float* __restrict__ out) {
    __shared__ float sA[BM * SA_STR];
    __shared__ float sB[KC * SB_STR];

    int tid = threadIdx.x, wid = tid >> 5, lane = tid & 31;
    int rowbase = blockIdx.x * BM;
    float alpha = __ldg(alphaPtr);
    float beta  = 1.0f - alpha;

    float acc[16][4];
    #pragma unroll
    for (int t = 0; t < 16; t++) { acc[t][0]=0.f; acc[t][1]=0.f; acc[t][2]=0.f; acc[t][3]=0.f; }

    for (int kc = 0; kc < 4; kc++) {
        #pragma unroll
        for (int it = 0; it < 4; it++) {
            int f4 = tid + it * 256;
            int r  = f4 >> 3;
            int q  = f4 & 7;
            int row = rowbase + r;
            float4 v = make_float4(0.f, 0.f, 0.f, 0.f);
            if (row < N_NODES)
                v = g_h2[(size_t)row * C4 + kc * 8 + q];
            float* d = sA + r * SA_STR + q * 4;
            d[0] = to_tf32(v.x); d[1] = to_tf32(v.y);
            d[2] = to_tf32(v.z); d[3] = to_tf32(v.w);
        }
        #pragma unroll
        for (int it = 0; it < 4; it++) {
            int f4 = tid + it * 256;
            int k  = f4 >> 5;
            int q  = f4 & 31;
            float4 v = __ldg((const float4*)(Wd + (size_t)(kc * KC + k) * C) + q);
            float* d = sB + k * SB_STR + q * 4;
            d[0] = to_tf32(v.x); d[1] = to_tf32(v.y);
            d[2] = to_tf32(v.z); d[3] = to_tf32(v.w);
        }
        __syncthreads();

        int r0 = wid * 16;
        #pragma unroll
        for (int ks = 0; ks < 4; ks++) {
            int k0 = ks * 8;
            int ar = r0 + (lane >> 2);
            int ac = k0 + (lane & 3);
            uint32_t a0 = __float_as_uint(sA[ar * SA_STR + ac]);
            uint32_t a1 = __float_as_uint(sA[(ar + 8) * SA_STR + ac]);
            uint32_t a2 = __float_as_uint(sA[ar * SA_STR + ac + 4]);
            uint32_t a3 = __float_as_uint(sA[(ar + 8) * SA_STR + ac + 4]);
            int bk = k0 + (lane & 3);
            int bn = lane >> 2;
            #pragma unroll
            for (int t = 0; t < 16; t++) {
                uint32_t b0 = __float_as_uint(sB[bk * SB_STR + t * 8 + bn]);
                uint32_t b1 = __float_as_uint(sB[(bk + 4) * SB_STR + t * 8 + bn]);
                mma8(acc[t], a0, a1, a2, a3, b0, b1);
            }
        }
        __syncthreads();
    }

    int rA = rowbase + wid * 16 + (lane >> 2);
    int rB = rA + 8;
    #pragma unroll
    for (int t = 0; t < 16; t++) {
        int cbase = t * 8 + (lane & 3) * 2;
        float2 b2 = __ldg((const float2*)(bd + cbase));
        if (rA < N_NODES) {
            float2 xv = __ldg((const float2*)(x + (size_t)rA * C + cbase));
            float2 o; o.x = alpha * (acc[t][0] + b2.x) + beta * xv.x;
                      o.y = alpha * (acc[t][1] + b2.y) + beta * xv.y;
            *(float2*)(out + (size_t)rA * C + cbase) = o;
        }
        if (rB < N_NODES) {
            float2 xv = __ldg((const float2*)(x + (size_t)rB * C + cbase));
            float2 o; o.x = alpha * (acc[t][2] + b2.x) + beta * xv.x;
                      o.y = alpha * (acc[t][3] + b2.y) + beta * xv.y;
            *(float2*)(out + (size_t)rB * C + cbase) = o;
        }
    }
}

// ================= launch =================
extern "C" void kernel_launch(void* const* d_in, const int* in_sizes, int n_in,
                              void* d_out, int out_size) {
    const float4* x   = (const float4*)d_in[0];
    const int*    ei  = (const int*)  d_in[1];
    const float*  W1l = (const float*)d_in[2];
    const float*  b1  = (const float*)d_in[3];
    const float*  W1r = (const float*)d_in[4];
    const float*  W2l = (const float*)d_in[5];
    const float*  b2  = (const float*)d_in[6];
    const float*  W2r = (const float*)d_in[7];
    const float*  Wd  = (const float*)d_in[8];
    const float*  bd  = (const float*)d_in[9];
    const float*  alp = (const float*)d_in[10];
    float* out = (float*)d_out;

    const int edgeBlocks = (N_EDGES + 255) / 256;
    const int cvtBlocks  = (N_NODES * C4 + 255) / 256;
    const int aggBlocks  = (N_NODES * 32 + 255) / 256;
    const int mmaBlocks  = (N_NODES + BM - 1) / BM;

    // x -> bf16 + CSR build
    k_cvt_x<<<cvtBlocks, 256>>>(x);
    k_csr_init<<<256, 256>>>();
    k_hist<<<edgeBlocks, 256>>>(ei);
    k_scan1<<<SCAN_NB, 256>>>();
    k_scan2<<<SCAN_NB, 256>>>();
    k_fill<<<edgeBlocks, 256>>>(ei);

    // Layer 1
    k_agg<<<aggBlocks, 256>>>(1);
    k_layer_mma<<<mmaBlocks, 256>>>((const float*)x, W1l, W1r, b1, /*out=h1*/0);

    // Layer 2
    k_agg<<<aggBlocks, 256>>>(0);
    k_layer_mma<<<mmaBlocks, 256>>>(nullptr, W2l, W2r, b2, /*out=h2*/1);

    // Decoder + residual
    k_dec_mma<<<mmaBlocks, 256>>>((const float*)x, Wd, bd, alp, out);
}